// round 1
// baseline (speedup 1.0000x reference)
#include <cuda_runtime.h>

// CharRNN: B=512, T=2048, VOCAB=96, EMBED=32, HIDDEN=128
// Strategy: fused persistent recurrence kernel.
//  - e@We^T + b_cell collapses to a 96x128 lookup table (Etab) in SMEM.
//  - 128 CTAs (one per SM wave), 4 batch rows each, 128 threads (thread j owns h[j]).
//  - All weights in SMEM, transposed for conflict-free access.
//  - h double-buffered in SMEM as [k][row4] float4 -> one LDS.128 broadcast feeds
//    two packed fma.rn.f32x2 (Blackwell f32x2 pipe, 2x fp32 throughput).
//  - One __syncthreads per timestep.

#define VOCABN 96
#define EMBEDN 32
#define HID    128
#define BATCH  512
#define TLEN   2048
#define BROWS  4
#define NBLK   (BATCH / BROWS)   // 128
#define NTHR   128

typedef unsigned long long u64;

__device__ __forceinline__ u64 ffma2(u64 a, u64 b, u64 c) {
    u64 d;
    asm("fma.rn.f32x2 %0, %1, %2, %3;" : "=l"(d) : "l"(a), "l"(b), "l"(c));
    return d;
}
__device__ __forceinline__ u64 pack2(float x, float y) {
    u64 d;
    asm("mov.b64 %0, {%1, %2};" : "=l"(d) : "f"(x), "f"(y));
    return d;
}
__device__ __forceinline__ float2 unpack2(u64 a) {
    float2 r;
    asm("mov.b64 {%0, %1}, %2;" : "=f"(r.x), "=f"(r.y) : "l"(a));
    return r;
}

// SMEM layout (floats):
//  Wh_s  : 128*128        = 16384   [k*128 + j]   (Wh transposed)
//  Wd_s  : 128*96         = 12288   [k*96  + v]   (W_dec transposed)
//  Et_s  : 96*128         = 12288   [v*128 + j]   (embed table incl. b_cell)
//  bd_s  : 96 (+pad 32)   = 128
//  h_s   : 2*128*4        = 1024    [buf][k*4 + r] (double buffer, float4/row-packed)
//  x_s   : 4*2048 ints    = 8192    [t*4 + r]
#define OFF_WH  0
#define OFF_WD  (OFF_WH + 128*128)
#define OFF_ET  (OFF_WD + 128*96)
#define OFF_BD  (OFF_ET + 96*128)
#define OFF_H   (OFF_BD + 128)
#define OFF_X   (OFF_H + 2*128*4)
#define SMEM_FLOATS (OFF_X + 4*2048)
#define SMEM_BYTES  (SMEM_FLOATS * 4)

__global__ void __launch_bounds__(NTHR, 1)
charrnn_kernel(const int* __restrict__ x,
               const float* __restrict__ h0,
               const float* __restrict__ emb,
               const float* __restrict__ Wcell,   // [128][160]: [:, :32]=We, [:, 32:]=Wh
               const float* __restrict__ bcell,   // [128]
               const float* __restrict__ Wdec,    // [96][128]
               const float* __restrict__ bdec,    // [96]
               float* __restrict__ out,           // [512][2048][96]
               float* __restrict__ hfin)          // [512][128] or null
{
    extern __shared__ float smem[];
    float* Wh_s = smem + OFF_WH;
    float* Wd_s = smem + OFF_WD;
    float* Et_s = smem + OFF_ET;
    float* bd_s = smem + OFF_BD;
    float* h_s  = smem + OFF_H;
    int*   x_s  = (int*)(smem + OFF_X);

    const int j  = threadIdx.x;          // hidden index (0..127)
    const int b0 = blockIdx.x * BROWS;   // first batch row of this block

    // ---------------- init: build SMEM tables (one-time) ----------------
    // Wh transposed: Wh_s[k*128 + j] = Wcell[j*160 + 32 + k]
    #pragma unroll 4
    for (int k = 0; k < HID; k++)
        Wh_s[k * HID + j] = Wcell[j * (EMBEDN + HID) + EMBEDN + k];

    // W_dec transposed: Wd_s[k*96 + v] = Wdec[v*128 + k]  (here j plays k)
    #pragma unroll 4
    for (int v = 0; v < VOCABN; v++)
        Wd_s[j * VOCABN + v] = Wdec[v * HID + j];

    // Embed table: Et_s[v*128 + j] = b_cell[j] + sum_k emb[v][k] * We[j][k]
    {
        float we[EMBEDN];
        #pragma unroll
        for (int k = 0; k < EMBEDN; k++)
            we[k] = Wcell[j * (EMBEDN + HID) + k];
        const float bc = bcell[j];
        for (int v = 0; v < VOCABN; v++) {
            float a = bc;
            #pragma unroll
            for (int k = 0; k < EMBEDN; k++)
                a = fmaf(emb[v * EMBEDN + k], we[k], a);
            Et_s[v * HID + j] = a;
        }
    }

    if (j < VOCABN) bd_s[j] = bdec[j];

    // Preload this block's token indices: x_s[t*4 + r] = x[(b0+r)*T + t]
    for (int i = j; i < BROWS * TLEN; i += NTHR) {
        int t = i >> 2, r = i & 3;
        x_s[i] = x[(b0 + r) * TLEN + t];
    }

    // Initial h into buffer 0: h_s[k*4 + r]
    #pragma unroll
    for (int r = 0; r < BROWS; r++)
        h_s[j * BROWS + r] = h0[(b0 + r) * HID + j];

    __syncthreads();

    float hn0 = 0.f, hn1 = 0.f, hn2 = 0.f, hn3 = 0.f;

    // ---------------- main recurrence ----------------
    #pragma unroll 1
    for (int t = 0; t < TLEN; t++) {
        const float* hp = h_s + (t & 1) * (HID * BROWS);         // h_{t-1}
        float*       hq = h_s + ((t + 1) & 1) * (HID * BROWS);   // h_t

        // cell: acc[r] = Etab[x_t[r]][j] + sum_k Wh[j][k] * h_prev[r][k]
        const int4 iv = ((const int4*)x_s)[t];
        u64 acc01 = pack2(Et_s[iv.x * HID + j], Et_s[iv.y * HID + j]);
        u64 acc23 = pack2(Et_s[iv.z * HID + j], Et_s[iv.w * HID + j]);

        const u64* hp2 = (const u64*)hp;   // [k][pair] pairs: (r0,r1),(r2,r3)
        #pragma unroll 16
        for (int k = 0; k < HID; k++) {
            float w = Wh_s[k * HID + j];
            u64 wp = pack2(w, w);
            u64 h01 = hp2[k * 2 + 0];
            u64 h23 = hp2[k * 2 + 1];
            acc01 = ffma2(h01, wp, acc01);
            acc23 = ffma2(h23, wp, acc23);
        }

        float2 a01 = unpack2(acc01), a23 = unpack2(acc23);
        hn0 = tanhf(a01.x); hn1 = tanhf(a01.y);
        hn2 = tanhf(a23.x); hn3 = tanhf(a23.y);

        ((float4*)hq)[j] = make_float4(hn0, hn1, hn2, hn3);
        __syncthreads();

        // decoder: out[r][t][v] = b_dec[v] + sum_k Wdec[v][k] * h_t[r][k]
        if (j < VOCABN) {
            const float bv = bd_s[j];
            u64 d01 = pack2(bv, bv);
            u64 d23 = d01;
            const u64* hq2 = (const u64*)hq;
            #pragma unroll 16
            for (int k = 0; k < HID; k++) {
                float wd = Wd_s[k * VOCABN + j];
                u64 wdp = pack2(wd, wd);
                d01 = ffma2(hq2[k * 2 + 0], wdp, d01);
                d23 = ffma2(hq2[k * 2 + 1], wdp, d23);
            }
            float2 o01 = unpack2(d01), o23 = unpack2(d23);
            const size_t ob = (size_t)t * VOCABN + j;
            const size_t rowstride = (size_t)TLEN * VOCABN;
            out[(size_t)(b0 + 0) * rowstride + ob] = o01.x;
            out[(size_t)(b0 + 1) * rowstride + ob] = o01.y;
            out[(size_t)(b0 + 2) * rowstride + ob] = o23.x;
            out[(size_t)(b0 + 3) * rowstride + ob] = o23.y;
        }
    }

    // final hidden state
    if (hfin) {
        hfin[(b0 + 0) * HID + j] = hn0;
        hfin[(b0 + 1) * HID + j] = hn1;
        hfin[(b0 + 2) * HID + j] = hn2;
        hfin[(b0 + 3) * HID + j] = hn3;
    }
}

extern "C" void kernel_launch(void* const* d_in, const int* in_sizes, int n_in,
                              void* d_out, int out_size)
{
    const int*   x     = (const int*)d_in[0];
    const float* h0    = (const float*)d_in[1];
    const float* emb   = (const float*)d_in[2];
    const float* Wcell = (const float*)d_in[3];
    const float* bcell = (const float*)d_in[4];
    const float* Wdec  = (const float*)d_in[5];
    const float* bdec  = (const float*)d_in[6];

    float* out = (float*)d_out;
    const long long outs_elems = (long long)BATCH * TLEN * VOCABN;   // 100,663,296
    float* hfin = nullptr;
    if ((long long)out_size >= outs_elems + (long long)BATCH * HID)
        hfin = out + outs_elems;

    cudaFuncSetAttribute(charrnn_kernel,
                         cudaFuncAttributeMaxDynamicSharedMemorySize, SMEM_BYTES);

    charrnn_kernel<<<NBLK, NTHR, SMEM_BYTES>>>(x, h0, emb, Wcell, bcell,
                                               Wdec, bdec, out, hfin);
}